// round 3
// baseline (speedup 1.0000x reference)
#include <cuda_runtime.h>
#include <cuda_bf16.h>
#include <cstdint>

// Problem constants
constexpr int B_ = 2;
constexpr int H_ = 8;
constexpr int N_ = 4096;
constexpr int D_ = 64;
constexpr int DIM_ = 512;
constexpr int INNER_ = H_ * D_;          // 512
constexpr float SCALE_ = 0.125f;         // 64^-0.5
constexpr float LOG2E_ = 1.4426950408889634f;

// Scratch (device globals: allocation-free rule)
__device__ float g_q[(size_t)B_ * H_ * N_ * D_];     // [B,H,N,D]
__device__ float g_k[(size_t)B_ * H_ * N_ * D_];
__device__ float g_v[(size_t)B_ * H_ * N_ * D_];
__device__ float g_attn[(size_t)B_ * N_ * INNER_];   // [B,N,H*D]

// ---------------------------------------------------------------------------
// tf32 helpers
// ---------------------------------------------------------------------------
__device__ __forceinline__ float tf32r(float x) {
    uint32_t u;
    asm("cvt.rna.tf32.f32 %0, %1;" : "=r"(u) : "f"(x));
    return __uint_as_float(u);
}

__device__ __forceinline__ void mma_tf32(float* c, const uint32_t* a,
                                         uint32_t b0, uint32_t b1) {
    asm volatile(
        "mma.sync.aligned.m16n8k8.row.col.f32.tf32.tf32.f32 "
        "{%0,%1,%2,%3}, {%4,%5,%6,%7}, {%8,%9}, {%0,%1,%2,%3};\n"
        : "+f"(c[0]), "+f"(c[1]), "+f"(c[2]), "+f"(c[3])
        : "r"(a[0]), "r"(a[1]), "r"(a[2]), "r"(a[3]), "r"(b0), "r"(b1));
}

// Permutation for A-operand smem rows (64-col k-chunk):
//   col c -> (c&3)*16 + (c>>3)*2 + ((c>>2)&1)
// Permutation for B-operand smem rows (64 n values):
//   n -> (n&7)*8 + (n>>3)

// ---------------------------------------------------------------------------
// Kernel 1: QKV projection with tf32 tensor cores.
// C[m,e] = sum_k x[m,k]*w_qkv[e,k].  Tile 128(m) x 128(e), K-chunks of 64.
// 256 threads = 8 warps (4 m-rows x 2 e-cols of 32x64 warp tiles).
// ---------------------------------------------------------------------------
constexpr int GLDA = 68;    // As row stride
constexpr int GLDB = 132;   // Bs row stride
constexpr int GEMM_SMEM = (128 * GLDA + 64 * GLDB) * 4;   // 68608 B

__global__ __launch_bounds__(256, 1)
void qkv_tc_kernel(const float* __restrict__ x, const float* __restrict__ w)
{
    extern __shared__ float gsm[];
    float* As = gsm;                 // [128][GLDA]  A-perm per 64-k chunk
    float* Bs = As + 128 * GLDA;     // [64][GLDB]   Bs[k][nperm]

    const int tid  = threadIdx.x;
    const int wrp  = tid >> 5;
    const int lane = tid & 31;
    const int g    = lane >> 2;
    const int q    = lane & 3;
    const int m0   = blockIdx.y * 128;
    const int e0   = blockIdx.x * 128;

    const int lrow  = tid >> 1;          // 0..127
    const int chalf = (tid & 1) * 32;    // col half within 64-chunk

    const int r0 = (wrp >> 1) * 32;      // warp m-offset
    const int nc = (wrp & 1) * 64;       // warp e-offset

    float acc[2][8][4];
#pragma unroll
    for (int mt = 0; mt < 2; mt++)
#pragma unroll
        for (int nt = 0; nt < 8; nt++)
#pragma unroll
            for (int e = 0; e < 4; e++) acc[mt][nt][e] = 0.f;

    const float* agp = x + (size_t)(m0 + lrow) * DIM_ + chalf;
    const float* bgp = w + (size_t)(e0 + lrow) * DIM_ + chalf;
    const int epb = ((lrow & 63) & 7) * 8 + ((lrow & 63) >> 3) + (lrow >> 6) * 64;

    for (int kt = 0; kt < DIM_; kt += 64) {
        __syncthreads();
        // Load A chunk (A-perm)
        {
            float* dst = As + lrow * GLDA;
#pragma unroll
            for (int c4 = 0; c4 < 32; c4 += 4) {
                const int c = chalf + c4;
                float4 v = *(const float4*)(agp + kt + c4);
                const int base = ((c >> 3) << 1) + ((c >> 2) & 1);
                dst[((c + 0) & 3) * 16 + base] = tf32r(v.x);
                dst[((c + 1) & 3) * 16 + base] = tf32r(v.y);
                dst[((c + 2) & 3) * 16 + base] = tf32r(v.z);
                dst[((c + 3) & 3) * 16 + base] = tf32r(v.w);
            }
        }
        // Load B chunk transposed: Bs[k][nperm]
        {
#pragma unroll
            for (int c4 = 0; c4 < 32; c4 += 4) {
                const int c = chalf + c4;
                float4 v = *(const float4*)(bgp + kt + c4);
                Bs[(c + 0) * GLDB + epb] = tf32r(v.x);
                Bs[(c + 1) * GLDB + epb] = tf32r(v.y);
                Bs[(c + 2) * GLDB + epb] = tf32r(v.z);
                Bs[(c + 3) * GLDB + epb] = tf32r(v.w);
            }
        }
        __syncthreads();

#pragma unroll
        for (int kc = 0; kc < 8; kc++) {
            uint32_t a[2][4];
#pragma unroll
            for (int mt = 0; mt < 2; mt++) {
                const float* arow = As + (r0 + mt * 16 + g) * GLDA + q * 16 + kc * 2;
                float2 alo = *(const float2*)arow;
                float2 ahi = *(const float2*)(arow + 8 * GLDA);
                a[mt][0] = __float_as_uint(alo.x);
                a[mt][1] = __float_as_uint(ahi.x);
                a[mt][2] = __float_as_uint(alo.y);
                a[mt][3] = __float_as_uint(ahi.y);
            }
            const float* brow = Bs + (kc * 8 + q) * GLDB + nc + g * 8;
            float4 bl0 = *(const float4*)(brow);
            float4 bl1 = *(const float4*)(brow + 4);
            float4 bh0 = *(const float4*)(brow + 4 * GLDB);
            float4 bh1 = *(const float4*)(brow + 4 * GLDB + 4);
            const float blv[8] = {bl0.x, bl0.y, bl0.z, bl0.w, bl1.x, bl1.y, bl1.z, bl1.w};
            const float bhv[8] = {bh0.x, bh0.y, bh0.z, bh0.w, bh1.x, bh1.y, bh1.z, bh1.w};
#pragma unroll
            for (int nt = 0; nt < 8; nt++) {
                const uint32_t b0 = __float_as_uint(blv[nt]);
                const uint32_t b1 = __float_as_uint(bhv[nt]);
                mma_tf32(acc[0][nt], a[0], b0, b1);
                mma_tf32(acc[1][nt], a[1], b0, b1);
            }
        }
    }

    // Epilogue: scatter into g_q/g_k/g_v [B,H,N,D]
    const int e_half = e0 + nc;              // multiple of 64
    const int which  = e_half >> 9;
    const int hh     = (e_half >> 6) & 7;
    float* dst = (which == 0) ? g_q : (which == 1) ? g_k : g_v;

#pragma unroll
    for (int mt = 0; mt < 2; mt++) {
#pragma unroll
        for (int h = 0; h < 2; h++) {
            const int m  = m0 + r0 + mt * 16 + g + 8 * h;
            const int bb = m >> 12;
            const int n  = m & 4095;
            float* row = dst + (((size_t)(bb * H_ + hh) * N_) + n) * D_ + 2 * q;
#pragma unroll
            for (int nt = 0; nt < 8; nt++) {
                float2 v;
                v.x = acc[mt][nt][2 * h];
                v.y = acc[mt][nt][2 * h + 1];
                *(float2*)(row + nt * 8) = v;
            }
        }
    }
}

// ---------------------------------------------------------------------------
// Kernel 2: fused flash attention, tf32 mma, 256 threads (8 warps x 16 rows).
// ---------------------------------------------------------------------------
constexpr int LD2 = 68;
constexpr int ATTN2_SMEM = (128 + 64 + 64 + 128) * LD2 * 4;   // 104448 B

__global__ __launch_bounds__(256, 1)
void attn_tc_kernel()
{
    extern __shared__ float sm2[];
    float* Qp = sm2;                  // [128][LD2]  A-perm (scaled by SCALE*log2e)
    float* Kp = Qp + 128 * LD2;       // [64][LD2]   Kp[d][permB(j)]
    float* Vp = Kp + 64 * LD2;        // [64][LD2]   Vp[j][permB(d)]
    float* Pp = Vp + 64 * LD2;        // [128][LD2]  A-perm

    const int tid  = threadIdx.x;
    const int wrp  = tid >> 5;        // 0..7
    const int lane = tid & 31;
    const int g    = lane >> 2;
    const int q    = lane & 3;
    const int r0   = wrp * 16;

    const int bh  = blockIdx.y;
    const int qr0 = blockIdx.x * 128;

    const float* Q = g_q + (size_t)bh * N_ * D_;
    const float* K = g_k + (size_t)bh * N_ * D_;
    const float* V = g_v + (size_t)bh * N_ * D_;

    // ---- Load Q tile (scale*log2e + tf32 + A-perm). Half row per thread. ----
    {
        const int lrow  = tid >> 1;
        const int chalf = (tid & 1) * 32;
        const float* qrow = Q + (size_t)(qr0 + lrow) * D_ + chalf;
        float* dst = Qp + lrow * LD2;
        const float sc = SCALE_ * LOG2E_;
#pragma unroll
        for (int c4 = 0; c4 < 32; c4 += 4) {
            const int c = chalf + c4;
            float4 v = *(const float4*)(qrow + c4);
            const int base = ((c >> 3) << 1) + ((c >> 2) & 1);
            dst[((c + 0) & 3) * 16 + base] = tf32r(v.x * sc);
            dst[((c + 1) & 3) * 16 + base] = tf32r(v.y * sc);
            dst[((c + 2) & 3) * 16 + base] = tf32r(v.z * sc);
            dst[((c + 3) & 3) * 16 + base] = tf32r(v.w * sc);
        }
    }

    float o[8][4];
#pragma unroll
    for (int nt = 0; nt < 8; nt++)
#pragma unroll
        for (int e = 0; e < 4; e++) o[nt][e] = 0.f;
    float m_run[2] = {-1e30f, -1e30f};
    float l_run[2] = {0.f, 0.f};

    const int jl = tid & 63;             // key row this thread loads
    const int cq = (tid >> 6) * 16;      // col quarter (16 cols)
    const int jp = (jl & 7) * 8 + (jl >> 3);

    for (int jt = 0; jt < N_ / 64; jt++) {
        __syncthreads();

        // ---- Load K,V tile -> permuted smem (tf32) ----
        {
            const float* krow = K + (size_t)(jt * 64 + jl) * D_ + cq;
            const float* vrow = V + (size_t)(jt * 64 + jl) * D_ + cq;
            float* vdstbase = Vp + jl * LD2;
#pragma unroll
            for (int c4 = 0; c4 < 16; c4 += 4) {
                const int c = cq + c4;
                float4 kv = *(const float4*)(krow + c4);
                Kp[(c + 0) * LD2 + jp] = tf32r(kv.x);
                Kp[(c + 1) * LD2 + jp] = tf32r(kv.y);
                Kp[(c + 2) * LD2 + jp] = tf32r(kv.z);
                Kp[(c + 3) * LD2 + jp] = tf32r(kv.w);
                float4 vv = *(const float4*)(vrow + c4);
                float* vdst = vdstbase + (c >> 3);
                vdst[((c + 0) & 7) * 8] = tf32r(vv.x);
                vdst[((c + 1) & 7) * 8] = tf32r(vv.y);
                vdst[((c + 2) & 7) * 8] = tf32r(vv.z);
                vdst[((c + 3) & 7) * 8] = tf32r(vv.w);
            }
        }
        __syncthreads();

        // ---- GEMM1: S = Qs @ K^T  (warp: 16 x 64, K=64) ----
        float s[8][4];
#pragma unroll
        for (int nt = 0; nt < 8; nt++)
#pragma unroll
            for (int e = 0; e < 4; e++) s[nt][e] = 0.f;

#pragma unroll
        for (int kc = 0; kc < 8; kc++) {
            uint32_t a[4];
            {
                const float* arow = Qp + (r0 + g) * LD2 + q * 16 + kc * 2;
                float2 alo = *(const float2*)arow;
                float2 ahi = *(const float2*)(arow + 8 * LD2);
                a[0] = __float_as_uint(alo.x);
                a[1] = __float_as_uint(ahi.x);
                a[2] = __float_as_uint(alo.y);
                a[3] = __float_as_uint(ahi.y);
            }
            const float* brow = Kp + (kc * 8 + q) * LD2 + g * 8;
            float4 bl0 = *(const float4*)(brow);
            float4 bl1 = *(const float4*)(brow + 4);
            float4 bh0 = *(const float4*)(brow + 4 * LD2);
            float4 bh1 = *(const float4*)(brow + 4 * LD2 + 4);
            const float blv[8] = {bl0.x, bl0.y, bl0.z, bl0.w, bl1.x, bl1.y, bl1.z, bl1.w};
            const float bhv[8] = {bh0.x, bh0.y, bh0.z, bh0.w, bh1.x, bh1.y, bh1.z, bh1.w};
#pragma unroll
            for (int nt = 0; nt < 8; nt++)
                mma_tf32(s[nt], a, __float_as_uint(blv[nt]), __float_as_uint(bhv[nt]));
        }

        // ---- Online softmax in exp2 domain ----
#pragma unroll
        for (int h = 0; h < 2; h++) {
            float mloc = -1e30f;
#pragma unroll
            for (int nt = 0; nt < 8; nt++)
                mloc = fmaxf(mloc, fmaxf(s[nt][2 * h], s[nt][2 * h + 1]));
            mloc = fmaxf(mloc, __shfl_xor_sync(0xffffffffu, mloc, 1));
            mloc = fmaxf(mloc, __shfl_xor_sync(0xffffffffu, mloc, 2));
            const float mnew  = fmaxf(m_run[h], mloc);
            const float alpha = exp2f(m_run[h] - mnew);
            float rs = 0.f;
#pragma unroll
            for (int nt = 0; nt < 8; nt++) {
                const float p0 = exp2f(s[nt][2 * h]     - mnew);
                const float p1 = exp2f(s[nt][2 * h + 1] - mnew);
                s[nt][2 * h]     = p0;
                s[nt][2 * h + 1] = p1;
                rs += p0 + p1;
            }
            rs += __shfl_xor_sync(0xffffffffu, rs, 1);
            rs += __shfl_xor_sync(0xffffffffu, rs, 2);
            l_run[h] = l_run[h] * alpha + rs;
            m_run[h] = mnew;
#pragma unroll
            for (int nt = 0; nt < 8; nt++) {
                o[nt][2 * h]     *= alpha;
                o[nt][2 * h + 1] *= alpha;
            }
        }

        // ---- Store P (tf32, A-perm layout) ----
        {
            const int pos0 = ((2 * q) & 3) * 16 + (q >> 1);
            float* prow0 = Pp + (r0 + g) * LD2;
            float* prow1 = prow0 + 8 * LD2;
#pragma unroll
            for (int nt = 0; nt < 8; nt++) {
                prow0[pos0 + nt * 2]      = tf32r(s[nt][0]);
                prow0[pos0 + 16 + nt * 2] = tf32r(s[nt][1]);
                prow1[pos0 + nt * 2]      = tf32r(s[nt][2]);
                prow1[pos0 + 16 + nt * 2] = tf32r(s[nt][3]);
            }
        }
        __syncwarp();

        // ---- GEMM2: O += P @ V  (warp: 16 x 64, K=64) ----
#pragma unroll
        for (int kc = 0; kc < 8; kc++) {
            uint32_t a[4];
            {
                const float* arow = Pp + (r0 + g) * LD2 + q * 16 + kc * 2;
                float2 alo = *(const float2*)arow;
                float2 ahi = *(const float2*)(arow + 8 * LD2);
                a[0] = __float_as_uint(alo.x);
                a[1] = __float_as_uint(ahi.x);
                a[2] = __float_as_uint(alo.y);
                a[3] = __float_as_uint(ahi.y);
            }
            const float* brow = Vp + (kc * 8 + q) * LD2 + g * 8;
            float4 bl0 = *(const float4*)(brow);
            float4 bl1 = *(const float4*)(brow + 4);
            float4 bh0 = *(const float4*)(brow + 4 * LD2);
            float4 bh1 = *(const float4*)(brow + 4 * LD2 + 4);
            const float blv[8] = {bl0.x, bl0.y, bl0.z, bl0.w, bl1.x, bl1.y, bl1.z, bl1.w};
            const float bhv[8] = {bh0.x, bh0.y, bh0.z, bh0.w, bh1.x, bh1.y, bh1.z, bh1.w};
#pragma unroll
            for (int nt = 0; nt < 8; nt++)
                mma_tf32(o[nt], a, __float_as_uint(blv[nt]), __float_as_uint(bhv[nt]));
        }
    }

    // ---- Epilogue: normalize, write to g_attn [B,N,H*D] ----
    const int bb = bh >> 3;
    const int hh = bh & 7;
#pragma unroll
    for (int h = 0; h < 2; h++) {
        const float inv = 1.f / l_run[h];
        const int n = qr0 + r0 + g + 8 * h;
        float* row = g_attn + ((size_t)(bb * N_ + n)) * INNER_ + hh * 64 + 2 * q;
#pragma unroll
        for (int nt = 0; nt < 8; nt++) {
            float2 val;
            val.x = o[nt][2 * h]     * inv;
            val.y = o[nt][2 * h + 1] * inv;
            *(float2*)(row + nt * 8) = val;
        }
    }
}

// ---------------------------------------------------------------------------
// Kernel 3: output projection with tf32 tensor cores.
// out[m,d] = sum_e attn[m,e]*w_out[d,e] + b_out[d]
// ---------------------------------------------------------------------------
__global__ __launch_bounds__(256, 1)
void proj_tc_kernel(const float* __restrict__ w, const float* __restrict__ bias,
                    float* __restrict__ out)
{
    extern __shared__ float gsm[];
    float* As = gsm;
    float* Bs = As + 128 * GLDA;

    const int tid  = threadIdx.x;
    const int wrp  = tid >> 5;
    const int lane = tid & 31;
    const int g    = lane >> 2;
    const int q    = lane & 3;
    const int m0   = blockIdx.y * 128;
    const int n0   = blockIdx.x * 128;

    const int lrow  = tid >> 1;
    const int chalf = (tid & 1) * 32;

    const int r0 = (wrp >> 1) * 32;
    const int nc = (wrp & 1) * 64;

    float acc[2][8][4];
#pragma unroll
    for (int mt = 0; mt < 2; mt++)
#pragma unroll
        for (int nt = 0; nt < 8; nt++)
#pragma unroll
            for (int e = 0; e < 4; e++) acc[mt][nt][e] = 0.f;

    const float* agp = g_attn + (size_t)(m0 + lrow) * INNER_ + chalf;
    const float* bgp = w + (size_t)(n0 + lrow) * INNER_ + chalf;
    const int epb = ((lrow & 63) & 7) * 8 + ((lrow & 63) >> 3) + (lrow >> 6) * 64;

    for (int kt = 0; kt < INNER_; kt += 64) {
        __syncthreads();
        {
            float* dst = As + lrow * GLDA;
#pragma unroll
            for (int c4 = 0; c4 < 32; c4 += 4) {
                const int c = chalf + c4;
                float4 v = *(const float4*)(agp + kt + c4);
                const int base = ((c >> 3) << 1) + ((c >> 2) & 1);
                dst[((c + 0) & 3) * 16 + base] = tf32r(v.x);
                dst[((c + 1) & 3) * 16 + base] = tf32r(v.y);
                dst[((c + 2) & 3) * 16 + base] = tf32r(v.z);
                dst[((c + 3) & 3) * 16 + base] = tf32r(v.w);
            }
        }
        {
#pragma unroll
            for (int c4 = 0; c4 < 32; c4 += 4) {
                const int c = chalf + c4;
                float4 v = *(const float4*)(bgp + kt + c4);
                Bs[(c + 0) * GLDB + epb] = tf32r(v.x);
                Bs[(c + 1) * GLDB + epb] = tf32r(v.y);
                Bs[(c + 2) * GLDB + epb] = tf32r(v.z);
                Bs[(c + 3) * GLDB + epb] = tf32r(v.w);
            }
        }
        __syncthreads();

#pragma unroll
        for (int kc = 0; kc < 8; kc++) {
            uint32_t a[2][4];
#pragma unroll
            for (int mt = 0; mt < 2; mt++) {
                const float* arow = As + (r0 + mt * 16 + g) * GLDA + q * 16 + kc * 2;
                float2 alo = *(const float2*)arow;
                float2 ahi = *(const float2*)(arow + 8 * GLDA);
                a[mt][0] = __float_as_uint(alo.x);
                a[mt][1] = __float_as_uint(ahi.x);
                a[mt][2] = __float_as_uint(alo.y);
                a[mt][3] = __float_as_uint(ahi.y);
            }
            const float* brow = Bs + (kc * 8 + q) * GLDB + nc + g * 8;
            float4 bl0 = *(const float4*)(brow);
            float4 bl1 = *(const float4*)(brow + 4);
            float4 bh0 = *(const float4*)(brow + 4 * GLDB);
            float4 bh1 = *(const float4*)(brow + 4 * GLDB + 4);
            const float blv[8] = {bl0.x, bl0.y, bl0.z, bl0.w, bl1.x, bl1.y, bl1.z, bl1.w};
            const float bhv[8] = {bh0.x, bh0.y, bh0.z, bh0.w, bh1.x, bh1.y, bh1.z, bh1.w};
#pragma unroll
            for (int nt = 0; nt < 8; nt++) {
                const uint32_t b0 = __float_as_uint(blv[nt]);
                const uint32_t b1 = __float_as_uint(bhv[nt]);
                mma_tf32(acc[0][nt], a[0], b0, b1);
                mma_tf32(acc[1][nt], a[1], b0, b1);
            }
        }
    }

#pragma unroll
    for (int mt = 0; mt < 2; mt++) {
#pragma unroll
        for (int h = 0; h < 2; h++) {
            const int m = m0 + r0 + mt * 16 + g + 8 * h;
            float* row = out + (size_t)m * DIM_ + n0 + nc + 2 * q;
#pragma unroll
            for (int nt = 0; nt < 8; nt++) {
                float2 bv = *(const float2*)(bias + n0 + nc + nt * 8 + 2 * q);
                float2 v;
                v.x = acc[mt][nt][2 * h]     + bv.x;
                v.y = acc[mt][nt][2 * h + 1] + bv.y;
                *(float2*)(row + nt * 8) = v;
            }
        }
    }
}

// ---------------------------------------------------------------------------
extern "C" void kernel_launch(void* const* d_in, const int* in_sizes, int n_in,
                              void* d_out, int out_size)
{
    const float* x      = (const float*)d_in[0];   // [2,4096,512]
    const float* w_qkv  = (const float*)d_in[1];   // [1536,512]
    const float* w_out  = (const float*)d_in[2];   // [512,512]
    const float* b_out  = (const float*)d_in[3];   // [512]
    float* out = (float*)d_out;                    // [2,4096,512]

    cudaFuncSetAttribute(qkv_tc_kernel,
                         cudaFuncAttributeMaxDynamicSharedMemorySize, GEMM_SMEM);
    cudaFuncSetAttribute(attn_tc_kernel,
                         cudaFuncAttributeMaxDynamicSharedMemorySize, ATTN2_SMEM);
    cudaFuncSetAttribute(proj_tc_kernel,
                         cudaFuncAttributeMaxDynamicSharedMemorySize, GEMM_SMEM);

    qkv_tc_kernel<<<dim3(12, 64), 256, GEMM_SMEM>>>(x, w_qkv);
    attn_tc_kernel<<<dim3(N_ / 128, B_ * H_), 256, ATTN2_SMEM>>>();
    proj_tc_kernel<<<dim3(4, 64), 256, GEMM_SMEM>>>(w_out, b_out, out);
}

// round 4
// speedup vs baseline: 1.3651x; 1.3651x over previous
#include <cuda_runtime.h>
#include <cuda_bf16.h>
#include <cstdint>

// Problem constants
constexpr int B_ = 2;
constexpr int H_ = 8;
constexpr int N_ = 4096;
constexpr int D_ = 64;
constexpr int DIM_ = 512;
constexpr int INNER_ = H_ * D_;          // 512
constexpr float SCALE_ = 0.125f;         // 64^-0.5
constexpr float LOG2E_ = 1.4426950408889634f;

// Scratch (device globals: allocation-free rule)
__device__ float g_q[(size_t)B_ * H_ * N_ * D_];     // [B,H,N,D]
__device__ float g_k[(size_t)B_ * H_ * N_ * D_];
__device__ float g_v[(size_t)B_ * H_ * N_ * D_];
__device__ float g_attn[(size_t)B_ * N_ * INNER_];   // [B,N,H*D]

// ---------------------------------------------------------------------------
// tf32 helpers
// ---------------------------------------------------------------------------
__device__ __forceinline__ float tf32r(float x) {
    uint32_t u;
    asm("cvt.rna.tf32.f32 %0, %1;" : "=r"(u) : "f"(x));
    return __uint_as_float(u);
}

__device__ __forceinline__ void mma_tf32(float* c, const uint32_t* a,
                                         uint32_t b0, uint32_t b1) {
    asm volatile(
        "mma.sync.aligned.m16n8k8.row.col.f32.tf32.tf32.f32 "
        "{%0,%1,%2,%3}, {%4,%5,%6,%7}, {%8,%9}, {%0,%1,%2,%3};\n"
        : "+f"(c[0]), "+f"(c[1]), "+f"(c[2]), "+f"(c[3])
        : "r"(a[0]), "r"(a[1]), "r"(a[2]), "r"(a[3]), "r"(b0), "r"(b1));
}

// A-operand perm:  col c -> (c&3)*16 + (c>>3)*2 + ((c>>2)&1)
// B-operand perm:  n     -> (n&7)*8  + (n>>3)

// ---------------------------------------------------------------------------
// Kernel 1: QKV projection, tf32 tensor cores (unchanged from round 3)
// ---------------------------------------------------------------------------
constexpr int GLDA = 68;
constexpr int GLDB = 132;
constexpr int GEMM_SMEM = (128 * GLDA + 64 * GLDB) * 4;   // 68608 B

__global__ __launch_bounds__(256, 1)
void qkv_tc_kernel(const float* __restrict__ x, const float* __restrict__ w)
{
    extern __shared__ float gsm[];
    float* As = gsm;
    float* Bs = As + 128 * GLDA;

    const int tid  = threadIdx.x;
    const int wrp  = tid >> 5;
    const int lane = tid & 31;
    const int g    = lane >> 2;
    const int q    = lane & 3;
    const int m0   = blockIdx.y * 128;
    const int e0   = blockIdx.x * 128;

    const int lrow  = tid >> 1;
    const int chalf = (tid & 1) * 32;

    const int r0 = (wrp >> 1) * 32;
    const int nc = (wrp & 1) * 64;

    float acc[2][8][4];
#pragma unroll
    for (int mt = 0; mt < 2; mt++)
#pragma unroll
        for (int nt = 0; nt < 8; nt++)
#pragma unroll
            for (int e = 0; e < 4; e++) acc[mt][nt][e] = 0.f;

    const float* agp = x + (size_t)(m0 + lrow) * DIM_ + chalf;
    const float* bgp = w + (size_t)(e0 + lrow) * DIM_ + chalf;
    const int epb = ((lrow & 63) & 7) * 8 + ((lrow & 63) >> 3) + (lrow >> 6) * 64;

    for (int kt = 0; kt < DIM_; kt += 64) {
        __syncthreads();
        {
            float* dst = As + lrow * GLDA;
#pragma unroll
            for (int c4 = 0; c4 < 32; c4 += 4) {
                const int c = chalf + c4;
                float4 v = *(const float4*)(agp + kt + c4);
                const int base = ((c >> 3) << 1) + ((c >> 2) & 1);
                dst[((c + 0) & 3) * 16 + base] = tf32r(v.x);
                dst[((c + 1) & 3) * 16 + base] = tf32r(v.y);
                dst[((c + 2) & 3) * 16 + base] = tf32r(v.z);
                dst[((c + 3) & 3) * 16 + base] = tf32r(v.w);
            }
        }
        {
#pragma unroll
            for (int c4 = 0; c4 < 32; c4 += 4) {
                const int c = chalf + c4;
                float4 v = *(const float4*)(bgp + kt + c4);
                Bs[(c + 0) * GLDB + epb] = tf32r(v.x);
                Bs[(c + 1) * GLDB + epb] = tf32r(v.y);
                Bs[(c + 2) * GLDB + epb] = tf32r(v.z);
                Bs[(c + 3) * GLDB + epb] = tf32r(v.w);
            }
        }
        __syncthreads();

#pragma unroll
        for (int kc = 0; kc < 8; kc++) {
            uint32_t a[2][4];
#pragma unroll
            for (int mt = 0; mt < 2; mt++) {
                const float* arow = As + (r0 + mt * 16 + g) * GLDA + q * 16 + kc * 2;
                float2 alo = *(const float2*)arow;
                float2 ahi = *(const float2*)(arow + 8 * GLDA);
                a[mt][0] = __float_as_uint(alo.x);
                a[mt][1] = __float_as_uint(ahi.x);
                a[mt][2] = __float_as_uint(alo.y);
                a[mt][3] = __float_as_uint(ahi.y);
            }
            const float* brow = Bs + (kc * 8 + q) * GLDB + nc + g * 8;
            float4 bl0 = *(const float4*)(brow);
            float4 bl1 = *(const float4*)(brow + 4);
            float4 bh0 = *(const float4*)(brow + 4 * GLDB);
            float4 bh1 = *(const float4*)(brow + 4 * GLDB + 4);
            const float blv[8] = {bl0.x, bl0.y, bl0.z, bl0.w, bl1.x, bl1.y, bl1.z, bl1.w};
            const float bhv[8] = {bh0.x, bh0.y, bh0.z, bh0.w, bh1.x, bh1.y, bh1.z, bh1.w};
#pragma unroll
            for (int nt = 0; nt < 8; nt++) {
                const uint32_t b0 = __float_as_uint(blv[nt]);
                const uint32_t b1 = __float_as_uint(bhv[nt]);
                mma_tf32(acc[0][nt], a[0], b0, b1);
                mma_tf32(acc[1][nt], a[1], b0, b1);
            }
        }
    }

    const int e_half = e0 + nc;
    const int which  = e_half >> 9;
    const int hh     = (e_half >> 6) & 7;
    float* dst = (which == 0) ? g_q : (which == 1) ? g_k : g_v;

#pragma unroll
    for (int mt = 0; mt < 2; mt++) {
#pragma unroll
        for (int h = 0; h < 2; h++) {
            const int m  = m0 + r0 + mt * 16 + g + 8 * h;
            const int bb = m >> 12;
            const int n  = m & 4095;
            float* row = dst + (((size_t)(bb * H_ + hh) * N_) + n) * D_ + 2 * q;
#pragma unroll
            for (int nt = 0; nt < 8; nt++) {
                float2 v;
                v.x = acc[mt][nt][2 * h];
                v.y = acc[mt][nt][2 * h + 1];
                *(float2*)(row + nt * 8) = v;
            }
        }
    }
}

// ---------------------------------------------------------------------------
// Kernel 2: fused flash attention, tf32 mma.
// 256 threads = 8 warps x 32 query rows = 256-row Q tiles. Grid (16, 16).
// K/V tiles (64 keys) double-buffered in smem; register prefetch of the next
// tile's LDG at iteration top; ONE __syncthreads per tile.
// ---------------------------------------------------------------------------
constexpr int LD2 = 68;
constexpr int ATTN_Q_ROWS = 256;
constexpr int ATTN3_SMEM = (ATTN_Q_ROWS * 2 + 4 * 64) * LD2 * 4;  // 208896 B

__global__ __launch_bounds__(256, 1)
void attn_tc_kernel()
{
    extern __shared__ float sm2[];
    float* Qp   = sm2;                        // [256][LD2] A-perm (pre-scaled)
    float* Pp   = Qp + ATTN_Q_ROWS * LD2;     // [256][LD2] A-perm
    float* Kbuf = Pp + ATTN_Q_ROWS * LD2;     // [2][64][LD2]  Kp[d][permB(j)]
    float* Vbuf = Kbuf + 2 * 64 * LD2;        // [2][64][LD2]  Vp[j][permB(d)]

    const int tid  = threadIdx.x;
    const int wrp  = tid >> 5;        // 0..7
    const int lane = tid & 31;
    const int g    = lane >> 2;
    const int q    = lane & 3;
    const int r0   = wrp * 32;

    const int bh  = blockIdx.y;
    const int qr0 = blockIdx.x * ATTN_Q_ROWS;

    const float* Q = g_q + (size_t)bh * N_ * D_;
    const float* K = g_k + (size_t)bh * N_ * D_;
    const float* V = g_v + (size_t)bh * N_ * D_;

    // ---- Prologue: load Q tile (one row per thread, scale*log2e, A-perm) ----
    {
        const float* qrow = Q + (size_t)(qr0 + tid) * D_;
        float* dst = Qp + tid * LD2;
        const float sc = SCALE_ * LOG2E_;
#pragma unroll
        for (int c4 = 0; c4 < 64; c4 += 4) {
            float4 v = *(const float4*)(qrow + c4);
            const int base = ((c4 >> 3) << 1) + ((c4 >> 2) & 1);
            dst[((c4 + 0) & 3) * 16 + base] = tf32r(v.x * sc);
            dst[((c4 + 1) & 3) * 16 + base] = tf32r(v.y * sc);
            dst[((c4 + 2) & 3) * 16 + base] = tf32r(v.z * sc);
            dst[((c4 + 3) & 3) * 16 + base] = tf32r(v.w * sc);
        }
    }

    // K/V loader mapping: 4 threads per key row, 16 cols each
    const int jl  = tid & 63;
    const int c16 = (tid >> 6) * 16;
    const int jp  = (jl & 7) * 8 + (jl >> 3);

    // ---- Prologue: stage tile 0 into buffer 0 ----
    {
        const float* krow = K + (size_t)jl * D_ + c16;
        const float* vrow = V + (size_t)jl * D_ + c16;
        float* vdst = Vbuf + jl * LD2;
#pragma unroll
        for (int i = 0; i < 4; i++) {
            const int c = c16 + i * 4;
            float4 kv = *(const float4*)(krow + i * 4);
            Kbuf[(c + 0) * LD2 + jp] = tf32r(kv.x);
            Kbuf[(c + 1) * LD2 + jp] = tf32r(kv.y);
            Kbuf[(c + 2) * LD2 + jp] = tf32r(kv.z);
            Kbuf[(c + 3) * LD2 + jp] = tf32r(kv.w);
            float4 vv = *(const float4*)(vrow + i * 4);
            vdst[((c + 0) & 7) * 8 + ((c + 0) >> 3)] = tf32r(vv.x);
            vdst[((c + 1) & 7) * 8 + ((c + 1) >> 3)] = tf32r(vv.y);
            vdst[((c + 2) & 7) * 8 + ((c + 2) >> 3)] = tf32r(vv.z);
            vdst[((c + 3) & 7) * 8 + ((c + 3) >> 3)] = tf32r(vv.w);
        }
    }
    __syncthreads();

    float o[2][8][4];
#pragma unroll
    for (int mt = 0; mt < 2; mt++)
#pragma unroll
        for (int nt = 0; nt < 8; nt++)
#pragma unroll
            for (int e = 0; e < 4; e++) o[mt][nt][e] = 0.f;
    float m_run[2][2], l_run[2][2];
#pragma unroll
    for (int mt = 0; mt < 2; mt++)
#pragma unroll
        for (int h = 0; h < 2; h++) { m_run[mt][h] = -1e30f; l_run[mt][h] = 0.f; }

    constexpr int NT = N_ / 64;
    int cur = 0;

    for (int jt = 0; jt < NT; jt++) {
        // ---- Prefetch next tile into registers (LDG issued early) ----
        float4 kreg[4], vreg[4];
        const bool pf = (jt + 1 < NT);
        if (pf) {
            const float* krow = K + (size_t)((jt + 1) * 64 + jl) * D_ + c16;
            const float* vrow = V + (size_t)((jt + 1) * 64 + jl) * D_ + c16;
#pragma unroll
            for (int i = 0; i < 4; i++) {
                kreg[i] = *(const float4*)(krow + i * 4);
                vreg[i] = *(const float4*)(vrow + i * 4);
            }
        }

        const float* Kc = Kbuf + cur * 64 * LD2;
        const float* Vc = Vbuf + cur * 64 * LD2;

        // ---- GEMM1: S = Qs @ K^T  (warp: 32 x 64, K=64) ----
        float s[2][8][4];
#pragma unroll
        for (int mt = 0; mt < 2; mt++)
#pragma unroll
            for (int nt = 0; nt < 8; nt++)
#pragma unroll
                for (int e = 0; e < 4; e++) s[mt][nt][e] = 0.f;

#pragma unroll
        for (int kc = 0; kc < 8; kc++) {
            uint32_t a[2][4];
#pragma unroll
            for (int mt = 0; mt < 2; mt++) {
                const float* arow = Qp + (r0 + mt * 16 + g) * LD2 + q * 16 + kc * 2;
                float2 alo = *(const float2*)arow;
                float2 ahi = *(const float2*)(arow + 8 * LD2);
                a[mt][0] = __float_as_uint(alo.x);
                a[mt][1] = __float_as_uint(ahi.x);
                a[mt][2] = __float_as_uint(alo.y);
                a[mt][3] = __float_as_uint(ahi.y);
            }
            const float* brow = Kc + (kc * 8 + q) * LD2 + g * 8;
            float4 bl0 = *(const float4*)(brow);
            float4 bl1 = *(const float4*)(brow + 4);
            float4 bh0 = *(const float4*)(brow + 4 * LD2);
            float4 bh1 = *(const float4*)(brow + 4 * LD2 + 4);
            const float blv[8] = {bl0.x, bl0.y, bl0.z, bl0.w, bl1.x, bl1.y, bl1.z, bl1.w};
            const float bhv[8] = {bh0.x, bh0.y, bh0.z, bh0.w, bh1.x, bh1.y, bh1.z, bh1.w};
#pragma unroll
            for (int nt = 0; nt < 8; nt++) {
                const uint32_t b0 = __float_as_uint(blv[nt]);
                const uint32_t b1 = __float_as_uint(bhv[nt]);
                mma_tf32(s[0][nt], a[0], b0, b1);
                mma_tf32(s[1][nt], a[1], b0, b1);
            }
        }

        // ---- Online softmax (exp2 domain) ----
#pragma unroll
        for (int mt = 0; mt < 2; mt++) {
#pragma unroll
            for (int h = 0; h < 2; h++) {
                float mloc = -1e30f;
#pragma unroll
                for (int nt = 0; nt < 8; nt++)
                    mloc = fmaxf(mloc, fmaxf(s[mt][nt][2 * h], s[mt][nt][2 * h + 1]));
                mloc = fmaxf(mloc, __shfl_xor_sync(0xffffffffu, mloc, 1));
                mloc = fmaxf(mloc, __shfl_xor_sync(0xffffffffu, mloc, 2));
                const float mnew  = fmaxf(m_run[mt][h], mloc);
                const float alpha = exp2f(m_run[mt][h] - mnew);
                float rs = 0.f;
#pragma unroll
                for (int nt = 0; nt < 8; nt++) {
                    const float p0 = exp2f(s[mt][nt][2 * h]     - mnew);
                    const float p1 = exp2f(s[mt][nt][2 * h + 1] - mnew);
                    s[mt][nt][2 * h]     = p0;
                    s[mt][nt][2 * h + 1] = p1;
                    rs += p0 + p1;
                }
                rs += __shfl_xor_sync(0xffffffffu, rs, 1);
                rs += __shfl_xor_sync(0xffffffffu, rs, 2);
                l_run[mt][h] = l_run[mt][h] * alpha + rs;
                m_run[mt][h] = mnew;
#pragma unroll
                for (int nt = 0; nt < 8; nt++) {
                    o[mt][nt][2 * h]     *= alpha;
                    o[mt][nt][2 * h + 1] *= alpha;
                }
            }
        }

        // ---- Store P (tf32, A-perm; warp-private rows) ----
        {
            const int pos0 = ((2 * q) & 3) * 16 + (q >> 1);
#pragma unroll
            for (int mt = 0; mt < 2; mt++) {
                float* prow0 = Pp + (r0 + mt * 16 + g) * LD2;
                float* prow1 = prow0 + 8 * LD2;
#pragma unroll
                for (int nt = 0; nt < 8; nt++) {
                    prow0[pos0 + nt * 2]      = tf32r(s[mt][nt][0]);
                    prow0[pos0 + 16 + nt * 2] = tf32r(s[mt][nt][1]);
                    prow1[pos0 + nt * 2]      = tf32r(s[mt][nt][2]);
                    prow1[pos0 + 16 + nt * 2] = tf32r(s[mt][nt][3]);
                }
            }
        }
        __syncwarp();

        // ---- GEMM2: O += P @ V  (warp: 32 x 64, K=64) ----
#pragma unroll
        for (int kc = 0; kc < 8; kc++) {
            uint32_t a[2][4];
#pragma unroll
            for (int mt = 0; mt < 2; mt++) {
                const float* arow = Pp + (r0 + mt * 16 + g) * LD2 + q * 16 + kc * 2;
                float2 alo = *(const float2*)arow;
                float2 ahi = *(const float2*)(arow + 8 * LD2);
                a[mt][0] = __float_as_uint(alo.x);
                a[mt][1] = __float_as_uint(ahi.x);
                a[mt][2] = __float_as_uint(alo.y);
                a[mt][3] = __float_as_uint(ahi.y);
            }
            const float* brow = Vc + (kc * 8 + q) * LD2 + g * 8;
            float4 bl0 = *(const float4*)(brow);
            float4 bl1 = *(const float4*)(brow + 4);
            float4 bh0 = *(const float4*)(brow + 4 * LD2);
            float4 bh1 = *(const float4*)(brow + 4 * LD2 + 4);
            const float blv[8] = {bl0.x, bl0.y, bl0.z, bl0.w, bl1.x, bl1.y, bl1.z, bl1.w};
            const float bhv[8] = {bh0.x, bh0.y, bh0.z, bh0.w, bh1.x, bh1.y, bh1.z, bh1.w};
#pragma unroll
            for (int nt = 0; nt < 8; nt++) {
                const uint32_t b0 = __float_as_uint(blv[nt]);
                const uint32_t b1 = __float_as_uint(bhv[nt]);
                mma_tf32(o[0][nt], a[0], b0, b1);
                mma_tf32(o[1][nt], a[1], b0, b1);
            }
        }

        // ---- Drain prefetch into the other buffer ----
        if (pf) {
            const int nxt = cur ^ 1;
            float* kd = Kbuf + nxt * 64 * LD2;
            float* vd = Vbuf + nxt * 64 * LD2 + jl * LD2;
#pragma unroll
            for (int i = 0; i < 4; i++) {
                const int c = c16 + i * 4;
                kd[(c + 0) * LD2 + jp] = tf32r(kreg[i].x);
                kd[(c + 1) * LD2 + jp] = tf32r(kreg[i].y);
                kd[(c + 2) * LD2 + jp] = tf32r(kreg[i].z);
                kd[(c + 3) * LD2 + jp] = tf32r(kreg[i].w);
                vd[((c + 0) & 7) * 8 + ((c + 0) >> 3)] = tf32r(vreg[i].x);
                vd[((c + 1) & 7) * 8 + ((c + 1) >> 3)] = tf32r(vreg[i].y);
                vd[((c + 2) & 7) * 8 + ((c + 2) >> 3)] = tf32r(vreg[i].z);
                vd[((c + 3) & 7) * 8 + ((c + 3) >> 3)] = tf32r(vreg[i].w);
            }
        }
        __syncthreads();
        cur ^= 1;
    }

    // ---- Epilogue: normalize, write to g_attn [B,N,H*D] ----
    const int bb = bh >> 3;
    const int hh = bh & 7;
#pragma unroll
    for (int mt = 0; mt < 2; mt++) {
#pragma unroll
        for (int h = 0; h < 2; h++) {
            const float inv = 1.f / l_run[mt][h];
            const int n = qr0 + r0 + mt * 16 + g + 8 * h;
            float* row = g_attn + ((size_t)(bb * N_ + n)) * INNER_ + hh * 64 + 2 * q;
#pragma unroll
            for (int nt = 0; nt < 8; nt++) {
                float2 val;
                val.x = o[mt][nt][2 * h]     * inv;
                val.y = o[mt][nt][2 * h + 1] * inv;
                *(float2*)(row + nt * 8) = val;
            }
        }
    }
}

// ---------------------------------------------------------------------------
// Kernel 3: output projection, tf32 tensor cores (unchanged from round 3)
// ---------------------------------------------------------------------------
__global__ __launch_bounds__(256, 1)
void proj_tc_kernel(const float* __restrict__ w, const float* __restrict__ bias,
                    float* __restrict__ out)
{
    extern __shared__ float gsm[];
    float* As = gsm;
    float* Bs = As + 128 * GLDA;

    const int tid  = threadIdx.x;
    const int wrp  = tid >> 5;
    const int lane = tid & 31;
    const int g    = lane >> 2;
    const int q    = lane & 3;
    const int m0   = blockIdx.y * 128;
    const int n0   = blockIdx.x * 128;

    const int lrow  = tid >> 1;
    const int chalf = (tid & 1) * 32;

    const int r0 = (wrp >> 1) * 32;
    const int nc = (wrp & 1) * 64;

    float acc[2][8][4];
#pragma unroll
    for (int mt = 0; mt < 2; mt++)
#pragma unroll
        for (int nt = 0; nt < 8; nt++)
#pragma unroll
            for (int e = 0; e < 4; e++) acc[mt][nt][e] = 0.f;

    const float* agp = g_attn + (size_t)(m0 + lrow) * INNER_ + chalf;
    const float* bgp = w + (size_t)(n0 + lrow) * INNER_ + chalf;
    const int epb = ((lrow & 63) & 7) * 8 + ((lrow & 63) >> 3) + (lrow >> 6) * 64;

    for (int kt = 0; kt < INNER_; kt += 64) {
        __syncthreads();
        {
            float* dst = As + lrow * GLDA;
#pragma unroll
            for (int c4 = 0; c4 < 32; c4 += 4) {
                const int c = chalf + c4;
                float4 v = *(const float4*)(agp + kt + c4);
                const int base = ((c >> 3) << 1) + ((c >> 2) & 1);
                dst[((c + 0) & 3) * 16 + base] = tf32r(v.x);
                dst[((c + 1) & 3) * 16 + base] = tf32r(v.y);
                dst[((c + 2) & 3) * 16 + base] = tf32r(v.z);
                dst[((c + 3) & 3) * 16 + base] = tf32r(v.w);
            }
        }
        {
#pragma unroll
            for (int c4 = 0; c4 < 32; c4 += 4) {
                const int c = chalf + c4;
                float4 v = *(const float4*)(bgp + kt + c4);
                Bs[(c + 0) * GLDB + epb] = tf32r(v.x);
                Bs[(c + 1) * GLDB + epb] = tf32r(v.y);
                Bs[(c + 2) * GLDB + epb] = tf32r(v.z);
                Bs[(c + 3) * GLDB + epb] = tf32r(v.w);
            }
        }
        __syncthreads();

#pragma unroll
        for (int kc = 0; kc < 8; kc++) {
            uint32_t a[2][4];
#pragma unroll
            for (int mt = 0; mt < 2; mt++) {
                const float* arow = As + (r0 + mt * 16 + g) * GLDA + q * 16 + kc * 2;
                float2 alo = *(const float2*)arow;
                float2 ahi = *(const float2*)(arow + 8 * GLDA);
                a[mt][0] = __float_as_uint(alo.x);
                a[mt][1] = __float_as_uint(ahi.x);
                a[mt][2] = __float_as_uint(alo.y);
                a[mt][3] = __float_as_uint(ahi.y);
            }
            const float* brow = Bs + (kc * 8 + q) * GLDB + nc + g * 8;
            float4 bl0 = *(const float4*)(brow);
            float4 bl1 = *(const float4*)(brow + 4);
            float4 bh0 = *(const float4*)(brow + 4 * GLDB);
            float4 bh1 = *(const float4*)(brow + 4 * GLDB + 4);
            const float blv[8] = {bl0.x, bl0.y, bl0.z, bl0.w, bl1.x, bl1.y, bl1.z, bl1.w};
            const float bhv[8] = {bh0.x, bh0.y, bh0.z, bh0.w, bh1.x, bh1.y, bh1.z, bh1.w};
#pragma unroll
            for (int nt = 0; nt < 8; nt++) {
                const uint32_t b0 = __float_as_uint(blv[nt]);
                const uint32_t b1 = __float_as_uint(bhv[nt]);
                mma_tf32(acc[0][nt], a[0], b0, b1);
                mma_tf32(acc[1][nt], a[1], b0, b1);
            }
        }
    }

#pragma unroll
    for (int mt = 0; mt < 2; mt++) {
#pragma unroll
        for (int h = 0; h < 2; h++) {
            const int m = m0 + r0 + mt * 16 + g + 8 * h;
            float* row = out + (size_t)m * DIM_ + n0 + nc + 2 * q;
#pragma unroll
            for (int nt = 0; nt < 8; nt++) {
                float2 bv = *(const float2*)(bias + n0 + nc + nt * 8 + 2 * q);
                float2 v;
                v.x = acc[mt][nt][2 * h]     + bv.x;
                v.y = acc[mt][nt][2 * h + 1] + bv.y;
                *(float2*)(row + nt * 8) = v;
            }
        }
    }
}

// ---------------------------------------------------------------------------
extern "C" void kernel_launch(void* const* d_in, const int* in_sizes, int n_in,
                              void* d_out, int out_size)
{
    const float* x      = (const float*)d_in[0];   // [2,4096,512]
    const float* w_qkv  = (const float*)d_in[1];   // [1536,512]
    const float* w_out  = (const float*)d_in[2];   // [512,512]
    const float* b_out  = (const float*)d_in[3];   // [512]
    float* out = (float*)d_out;                    // [2,4096,512]

    cudaFuncSetAttribute(qkv_tc_kernel,
                         cudaFuncAttributeMaxDynamicSharedMemorySize, GEMM_SMEM);
    cudaFuncSetAttribute(attn_tc_kernel,
                         cudaFuncAttributeMaxDynamicSharedMemorySize, ATTN3_SMEM);
    cudaFuncSetAttribute(proj_tc_kernel,
                         cudaFuncAttributeMaxDynamicSharedMemorySize, GEMM_SMEM);

    qkv_tc_kernel<<<dim3(12, 64), 256, GEMM_SMEM>>>(x, w_qkv);
    attn_tc_kernel<<<dim3(N_ / ATTN_Q_ROWS, B_ * H_), 256, ATTN3_SMEM>>>();
    proj_tc_kernel<<<dim3(4, 64), 256, GEMM_SMEM>>>(w_out, b_out, out);
}